// round 1
// baseline (speedup 1.0000x reference)
#include <cuda_runtime.h>

#define Wd 256
#define Hd 256
#define Bd 64
#define NPIX (Bd*Hd*Wd)          // 4,194,304 per field
#define NV   (NPIX/4)            // float4 vectors
#define EPSf 1e-12f

// ---- iteration-invariant + dual-state scratch (static device arrays; no allocs) ----
__device__ __align__(16) float g_g2x[NPIX];
__device__ __align__(16) float g_g2y[NPIX];
__device__ __align__(16) float g_rc [NPIX];
__device__ __align__(16) float g_p11[NPIX];
__device__ __align__(16) float g_p12[NPIX];
__device__ __align__(16) float g_p21[NPIX];
__device__ __align__(16) float g_p22[NPIX];

union F4 { float4 v; float f[4]; };

__device__ __forceinline__ float4 ld4(const float* p) { return *reinterpret_cast<const float4*>(p); }
__device__ __forceinline__ void   st4(float* p, float4 v) { *reinterpret_cast<float4*>(p) = v; }

// ============================================================================
// Init: compute g2x, g2y (centered grads of y with x boundary rows/cols),
// rho_c = y - x, and the iteration-1 u-update (u=0, p=0 -> u = thresholded v).
// ============================================================================
__global__ void __launch_bounds__(256) k_init(
    const float* __restrict__ x, const float* __restrict__ y,
    const float* __restrict__ tp, const float* __restrict__ lp,
    float* __restrict__ u1, float* __restrict__ u2)
{
    int v = blockIdx.x * blockDim.x + threadIdx.x;
    if (v >= NV) return;
    int idx = v << 2;
    int j4 = idx & (Wd - 1);
    int i  = (idx >> 8) & (Hd - 1);

    float ts  = tp[0];
    float l_t = lp[0] * ts;

    F4 X, Y, Yu, Yd, Xu, Xd;
    X.v = ld4(x + idx);
    Y.v = ld4(y + idx);
    float yl = (j4 > 0)       ? y[idx - 1] : 0.f;
    float yr = (j4 + 4 < Wd)  ? y[idx + 4] : 0.f;
    Yu.v = (i > 0)      ? ld4(y + idx - Wd) : make_float4(0,0,0,0);
    Yd.v = (i < Hd - 1) ? ld4(y + idx + Wd) : make_float4(0,0,0,0);
    Xd.v = (i == 0)      ? ld4(x + idx + Wd) : make_float4(0,0,0,0);
    Xu.v = (i == Hd - 1) ? ld4(x + idx - Wd) : make_float4(0,0,0,0);

    F4 GX, GY, RC, O1, O2;
#pragma unroll
    for (int k = 0; k < 4; k++) {
        int j = j4 + k;
        float gx;
        if (j == 0)            gx = 0.5f * (X.f[1] - X.f[0]);
        else if (j == Wd - 1)  gx = 0.5f * (X.f[3] - X.f[2]);
        else {
            float yn = (k < 3) ? Y.f[k + 1] : yr;
            float yp = (k > 0) ? Y.f[k - 1] : yl;
            gx = 0.5f * (yn - yp);
        }
        float gy;
        if (i == 0)            gy = 0.5f * (Xd.f[k] - X.f[k]);
        else if (i == Hd - 1)  gy = 0.5f * (X.f[k] - Xu.f[k]);
        else                   gy = 0.5f * (Yd.f[k] - Yu.f[k]);

        float rc = Y.f[k] - X.f[k];
        GX.f[k] = gx; GY.f[k] = gy; RC.f[k] = rc;

        // iteration-1 u update (u=0, div(p)=0)
        float rho  = rc + EPSf;
        float grad = gx * gx + gy * gy + EPSf;
        float lg   = l_t * grad;
        float v1, v2;
        if      (rho < -lg)   { v1 =  l_t * gx; v2 =  l_t * gy; }
        else if (rho >  lg)   { v1 = -l_t * gx; v2 = -l_t * gy; }
        else if (grad > EPSf) { float s = -rho / grad; v1 = s * gx; v2 = s * gy; }
        else                  { v1 = 0.f; v2 = 0.f; }
        O1.f[k] = v1; O2.f[k] = v2;
    }
    st4(g_g2x + idx, GX.v);
    st4(g_g2y + idx, GY.v);
    st4(g_rc  + idx, RC.v);
    st4(u1 + idx, O1.v);
    st4(u2 + idx, O2.v);
}

// ============================================================================
// P update: forward-difference grads of u1,u2 then dual projection.
// FIRST=true: previous p is identically zero (skip loads).
// ============================================================================
template <bool FIRST>
__global__ void __launch_bounds__(256) k_update_p(
    const float* __restrict__ tp, const float* __restrict__ ap,
    const float* __restrict__ u1, const float* __restrict__ u2)
{
    int v = blockIdx.x * blockDim.x + threadIdx.x;
    if (v >= NV) return;
    int idx = v << 2;
    int j4 = idx & (Wd - 1);
    int i  = (idx >> 8) & (Hd - 1);

    float taut = ap[0] / tp[0];

    F4 U1, U2, U1d, U2d;
    U1.v = ld4(u1 + idx);
    U2.v = ld4(u2 + idx);
    float u1r = (j4 + 4 < Wd) ? u1[idx + 4] : 0.f;
    float u2r = (j4 + 4 < Wd) ? u2[idx + 4] : 0.f;
    bool has_down = (i < Hd - 1);
    U1d.v = has_down ? ld4(u1 + idx + Wd) : make_float4(0,0,0,0);
    U2d.v = has_down ? ld4(u2 + idx + Wd) : make_float4(0,0,0,0);

    F4 P11, P12, P21, P22;
    if (!FIRST) {
        P11.v = ld4(g_p11 + idx);
        P12.v = ld4(g_p12 + idx);
        P21.v = ld4(g_p21 + idx);
        P22.v = ld4(g_p22 + idx);
    }

    F4 O11, O12, O21, O22;
#pragma unroll
    for (int k = 0; k < 4; k++) {
        int j = j4 + k;
        float u1x = (j < Wd - 1) ? ((k < 3) ? U1.f[k + 1] : u1r) - U1.f[k] : 0.f;
        float u2x = (j < Wd - 1) ? ((k < 3) ? U2.f[k + 1] : u2r) - U2.f[k] : 0.f;
        float u1y = has_down ? (U1d.f[k] - U1.f[k]) : 0.f;
        float u2y = has_down ? (U2d.f[k] - U2.f[k]) : 0.f;

        float n1 = sqrtf(u1x * u1x + u1y * u1y + EPSf);
        float n2 = sqrtf(u2x * u2x + u2y * u2y + EPSf);
        float f1 = 1.0f / (1.0f + taut * n1);
        float f2 = 1.0f / (1.0f + taut * n2);

        float p11o = FIRST ? 0.f : P11.f[k];
        float p12o = FIRST ? 0.f : P12.f[k];
        float p21o = FIRST ? 0.f : P21.f[k];
        float p22o = FIRST ? 0.f : P22.f[k];

        O11.f[k] = (p11o + taut * u1x) * f1;
        O12.f[k] = (p12o + taut * u1y) * f1;
        O21.f[k] = (p21o + taut * u2x) * f2;
        O22.f[k] = (p22o + taut * u2y) * f2;
    }
    st4(g_p11 + idx, O11.v);
    st4(g_p12 + idx, O12.v);
    st4(g_p21 + idx, O21.v);
    st4(g_p22 + idx, O22.v);
}

// ============================================================================
// U update: thresholding step + u = v + ts * div(p)
// div_x(p)[j] = (j==0) ? p[j] : p[j]-p[j-1]   (p last col is exactly 0)
// div_y(p)[i] = (i==0) ? p[i] : p[i]-p[i-W]   (p last row is exactly 0)
// ============================================================================
__global__ void __launch_bounds__(256) k_update_u(
    const float* __restrict__ tp, const float* __restrict__ lp,
    float* __restrict__ u1, float* __restrict__ u2)
{
    int v = blockIdx.x * blockDim.x + threadIdx.x;
    if (v >= NV) return;
    int idx = v << 2;
    int j4 = idx & (Wd - 1);
    int i  = (idx >> 8) & (Hd - 1);

    float ts  = tp[0];
    float l_t = lp[0] * ts;

    F4 U1, U2, GX, GY, RC, P11, P12, P21, P22, P12u, P22u;
    U1.v  = ld4(u1 + idx);
    U2.v  = ld4(u2 + idx);
    GX.v  = ld4(g_g2x + idx);
    GY.v  = ld4(g_g2y + idx);
    RC.v  = ld4(g_rc + idx);
    P11.v = ld4(g_p11 + idx);
    P12.v = ld4(g_p12 + idx);
    P21.v = ld4(g_p21 + idx);
    P22.v = ld4(g_p22 + idx);
    float p11l = (j4 > 0) ? g_p11[idx - 1] : 0.f;
    float p21l = (j4 > 0) ? g_p21[idx - 1] : 0.f;
    bool has_up = (i > 0);
    P12u.v = has_up ? ld4(g_p12 + idx - Wd) : make_float4(0,0,0,0);
    P22u.v = has_up ? ld4(g_p22 + idx - Wd) : make_float4(0,0,0,0);

    F4 O1, O2;
#pragma unroll
    for (int k = 0; k < 4; k++) {
        int j = j4 + k;
        float lft11 = (k > 0) ? P11.f[k - 1] : p11l;
        float lft21 = (k > 0) ? P21.f[k - 1] : p21l;
        float dx1 = (j == 0) ? P11.f[k] : (P11.f[k] - lft11);
        float dx2 = (j == 0) ? P21.f[k] : (P21.f[k] - lft21);
        float dy1 = has_up ? (P12.f[k] - P12u.f[k]) : P12.f[k];
        float dy2 = has_up ? (P22.f[k] - P22u.f[k]) : P22.f[k];

        float gx = GX.f[k], gy = GY.f[k];
        float rho  = RC.f[k] + gx * U1.f[k] + gy * U2.f[k] + EPSf;
        float grad = gx * gx + gy * gy + EPSf;
        float lg   = l_t * grad;
        float v1, v2;
        if      (rho < -lg)   { v1 =  l_t * gx; v2 =  l_t * gy; }
        else if (rho >  lg)   { v1 = -l_t * gx; v2 = -l_t * gy; }
        else if (grad > EPSf) { float s = -rho / grad; v1 = s * gx; v2 = s * gy; }
        else                  { v1 = 0.f; v2 = 0.f; }

        O1.f[k] = U1.f[k] + v1 + ts * (dx1 + dy1);
        O2.f[k] = U2.f[k] + v2 + ts * (dx2 + dy2);
    }
    st4(u1 + idx, O1.v);
    st4(u2 + idx, O2.v);
}

// ============================================================================
// Launch: init(+U1), then P1, U2, P2, ..., P9, U10  (final P skipped)
// ============================================================================
extern "C" void kernel_launch(void* const* d_in, const int* in_sizes, int n_in,
                              void* d_out, int out_size)
{
    const float* x = (const float*)d_in[0];
    const float* y = (const float*)d_in[1];
    // d_in[2..7]: conv weights (fixed stencils, not needed)
    const float* t = (const float*)d_in[8];
    const float* l = (const float*)d_in[9];
    const float* a = (const float*)d_in[10];

    float* u1 = (float*)d_out;
    float* u2 = u1 + NPIX;

    const int threads = 256;
    const int blocks  = (NV + threads - 1) / threads;

    k_init<<<blocks, threads>>>(x, y, t, l, u1, u2);          // g2x,g2y,rc + U1
    k_update_p<true><<<blocks, threads>>>(t, a, u1, u2);      // P1 (p_old = 0)
    for (int it = 0; it < 9; ++it) {
        k_update_u<<<blocks, threads>>>(t, l, u1, u2);        // U2..U10
        if (it < 8)
            k_update_p<false><<<blocks, threads>>>(t, a, u1, u2); // P2..P9
    }
}